// round 1
// baseline (speedup 1.0000x reference)
#include <cuda_runtime.h>
#include <math.h>

// ---------------- problem constants ----------------
#define B_    256
#define Nn    21
#define PHs   12
#define FEAT  8
#define INP_  256
#define LAT_  64
#define HID_  512
#define OUTD  128
#define NT_   4
#define IN0_  328   // FEAT + LAT + INP
#define HZ_   320   // LAT + INP
#define G3_   1536  // 3*HID
#define BN_   (B_*Nn)

// output packing: dq (B,PH,N,4) | cov (B,PH,N,6) | x_t (B,N,8)
#define OFF_DQ   0
#define OFF_COV  (B_*PHs*Nn*4)              // 258048
#define OFF_XT   (OFF_COV + B_*PHs*Nn*6)    // 645120

// ---------------- device scratch (no allocations allowed) ----------------
__device__ float g_xin[BN_*IN0_];     // [x_{t-1}(8), z(64), h(256)]
__device__ float g_base[BN_*G3_];     // h_z part of Wih + bih (step-invariant)
__device__ float g_hr[BN_*G3_];       // h_c * Whh^T + bhh (pre-mix)
__device__ float g_tmp0[BN_*HID_];    // pre-mix rnn_h
__device__ float g_h[2][BN_*HID_];    // GRU hidden ping-pong
__device__ float g_y[BN_*HID_];       // tanh(h)
__device__ float g_pq[BN_*OUTD];      // y*Wq^T + bq (pre-mix)
__device__ float g_pc[BN_*OUTD];
__device__ float g_ys[BN_*OUTD];
__device__ float g_yc[BN_*OUTD];
__device__ float g_xc[BN_*FEAT];
__device__ float g_qc[BN_*4];
__device__ float g_G0n[Nn*Nn], g_Gn[Nn*Nn], g_Gqn[Nn*Nn], g_Gcn[Nn*Nn];

// ---------------- small prep kernels ----------------
__global__ void knorms(const float* __restrict__ G0, const float* __restrict__ Grnn,
                       const float* __restrict__ GA, const float* __restrict__ Gq,
                       const float* __restrict__ Gc)
{
    int i = threadIdx.x;
    if (i >= 4*Nn) return;
    int mat = i / Nn, r = i % Nn;
    const float* src = (mat==0)?G0:(mat==1)?Grnn:(mat==2)?Gq:Gc;
    float* dst = (mat==0)?g_G0n:(mat==1)?g_Gn:(mat==2)?g_Gqn:g_Gcn;
    float s = 0.f;
    for (int m = 0; m < Nn; m++) s += fabsf(src[r*Nn+m]);
    s = fmaxf(s, 1e-12f);
    for (int m = 0; m < Nn; m++) {
        float v = src[r*Nn+m] / s;
        if (mat == 1) v += GA[r*Nn+m];
        dst[r*Nn+m] = v;
    }
}

__global__ void kprep(const float* __restrict__ x, const float* __restrict__ h,
                      const float* __restrict__ z, const float* __restrict__ qt,
                      float* __restrict__ out)
{
    int idx = blockIdx.x * blockDim.x + threadIdx.x;
    if (idx < BN_*IN0_) {
        int bn = idx / IN0_, k = idx % IN0_;
        int b = bn / Nn, n = bn % Nn;
        float v;
        if (k < FEAT)            v = x[((b*2 + 0)*Nn + n)*FEAT + k];          // x_{t-1}
        else if (k < FEAT+LAT_)  v = z[bn*LAT_ + (k - FEAT)];
        else                     v = h[bn*INP_ + (k - FEAT - LAT_)];
        g_xin[idx] = v;
    }
    if (idx < BN_*FEAT) {
        int bn = idx / FEAT, f = idx % FEAT;
        int b = bn / Nn, n = bn % Nn;
        float xv = x[((b*2 + 1)*Nn + n)*FEAT + f];                            // x_t
        g_xc[idx] = xv;
        out[OFF_XT + idx] = xv;
    }
    if (idx < BN_*4) g_qc[idx] = qt[idx];
}

// ---------------- tiled fp32 GEMM: C[b,n,g] = bias[n,g] + sum_k A[b,n,aoff+k]*W[T[n],g,woff+k]
// tile 64(B) x 64(G) x 16(K), 256 threads, 4x4 microtile with float4 smem access
__global__ void kgemm(int asel, int lda, int aoff,
                      const float* __restrict__ W, int ldw, int woff,
                      int G, int K,
                      const float* __restrict__ bias,
                      int csel,
                      const int* __restrict__ T)
{
    const float* A = (asel==0)?g_xin : (asel==1)?g_h[0] : (asel==2)?g_h[1] : g_y;
    float* C = (csel==0)?g_tmp0 : (csel==1)?g_base : (csel==2)?g_hr : (csel==3)?g_pq : g_pc;

    int n = blockIdx.z;
    int t = T[n];
    int b0 = blockIdx.x * 64;
    int g0 = blockIdx.y * 64;

    __shared__ float As[16][64];
    __shared__ float Ws[16][64];

    float acc[4][4] = {};
    int tid = threadIdx.x;
    const float* Wt = W + ((size_t)t * G + g0) * ldw + woff;
    const float* An = A + (size_t)n * lda + aoff;

    for (int k0 = 0; k0 < K; k0 += 16) {
        #pragma unroll 4
        for (int i = tid; i < 64*16; i += 256) {
            int r = i >> 4, kk = i & 15;
            int k = k0 + kk;
            As[kk][r] = (k < K) ? An[((size_t)(b0 + r) * Nn) * lda + k] : 0.f;
            Ws[kk][r] = (k < K) ? Wt[(size_t)r * ldw + k] : 0.f;
        }
        __syncthreads();
        int tr = (tid >> 4) * 4, tc = (tid & 15) * 4;
        #pragma unroll
        for (int kk = 0; kk < 16; kk++) {
            float4 a = *(const float4*)&As[kk][tr];
            float4 w = *(const float4*)&Ws[kk][tc];
            acc[0][0] += a.x*w.x; acc[0][1] += a.x*w.y; acc[0][2] += a.x*w.z; acc[0][3] += a.x*w.w;
            acc[1][0] += a.y*w.x; acc[1][1] += a.y*w.y; acc[1][2] += a.y*w.z; acc[1][3] += a.y*w.w;
            acc[2][0] += a.z*w.x; acc[2][1] += a.z*w.y; acc[2][2] += a.z*w.z; acc[2][3] += a.z*w.w;
            acc[3][0] += a.w*w.x; acc[3][1] += a.w*w.y; acc[3][2] += a.w*w.z; acc[3][3] += a.w*w.w;
        }
        __syncthreads();
    }

    int tr = (tid >> 4) * 4, tc = (tid & 15) * 4;
    float4 bv = *(const float4*)&bias[(size_t)n * G + g0 + tc];
    #pragma unroll
    for (int i = 0; i < 4; i++) {
        float4 o;
        o.x = acc[i][0] + bv.x; o.y = acc[i][1] + bv.y;
        o.z = acc[i][2] + bv.z; o.w = acc[i][3] + bv.w;
        *(float4*)&C[(((size_t)(b0 + tr + i)) * Nn + n) * G + g0 + tc] = o;
    }
}

// ---------------- rnn_h init mix: h0[b,n,c] = sum_m G0n[n,m]*tmp0[b,m,c]
__global__ void kmix_rnnh()
{
    int b = blockIdx.x, c0 = blockIdx.y * 64;
    __shared__ float sh[Nn][64];
    __shared__ float sG[Nn*Nn];
    int tid = threadIdx.x;
    for (int i = tid; i < Nn*Nn; i += 256) sG[i] = g_G0n[i];
    for (int i = tid; i < Nn*64; i += 256) {
        int m = i >> 6, c = i & 63;
        sh[m][c] = g_tmp0[((size_t)(b*Nn) + m) * HID_ + c0 + c];
    }
    __syncthreads();
    for (int i = tid; i < Nn*64; i += 256) {
        int n = i >> 6, c = i & 63;
        float s = 0.f;
        #pragma unroll
        for (int m = 0; m < Nn; m++) s += sG[n*Nn+m] * sh[m][c];
        g_h[0][((size_t)(b*Nn) + n) * HID_ + c0 + c] = s;
    }
}

// ---------------- per-step: graph mix of xr/hr + GRU gates
__global__ void kgates(const float* __restrict__ Wih, const int* __restrict__ T, int cur)
{
    int b = blockIdx.x, c0 = blockIdx.y * 64;
    __shared__ float sx[3][Nn][64];
    __shared__ float shh[3][Nn][64];
    __shared__ float sG[Nn*Nn];
    int tid = threadIdx.x;
    for (int i = tid; i < Nn*Nn; i += 256) sG[i] = g_Gn[i];
    for (int i = tid; i < 3*Nn*64; i += 256) {
        int s = i / (Nn*64), rem = i % (Nn*64);
        int m = rem >> 6, c = rem & 63;
        int g = s*HID_ + c0 + c;
        int t = T[m];
        const float* wx = Wih + ((size_t)t * G3_ + g) * IN0_;
        const float* xc = g_xc + (b*Nn + m) * FEAT;
        float acc = g_base[((size_t)(b*Nn) + m) * G3_ + g];
        #pragma unroll
        for (int q = 0; q < FEAT; q++) acc += xc[q] * wx[q];
        sx[s][m][c]  = acc;
        shh[s][m][c] = g_hr[((size_t)(b*Nn) + m) * G3_ + g];
    }
    __syncthreads();
    for (int i = tid; i < Nn*64; i += 256) {
        int n = i >> 6, c = i & 63;
        float ir=0,iz=0,ic=0,hr_=0,hz2=0,hc2=0;
        #pragma unroll
        for (int m = 0; m < Nn; m++) {
            float gw = sG[n*Nn+m];
            ir  += gw*sx[0][m][c];  iz  += gw*sx[1][m][c];  ic  += gw*sx[2][m][c];
            hr_ += gw*shh[0][m][c]; hz2 += gw*shh[1][m][c]; hc2 += gw*shh[2][m][c];
        }
        float r  = 1.f / (1.f + expf(-(ir + hr_)));
        float zg = 1.f / (1.f + expf(-(iz + hz2)));
        float nn = tanhf(ic + r*hc2);
        size_t hidx = ((size_t)(b*Nn) + n) * HID_ + c0 + c;
        float hc = g_h[cur][hidx];
        float hnew = (1.f - zg)*nn + zg*hc;
        g_h[cur^1][hidx] = hnew;
        g_y[hidx] = tanhf(hnew);
    }
}

// ---------------- per-step: output mixes ys/yc
__global__ void kmixout()
{
    int b = blockIdx.x;
    __shared__ float sq[Nn][OUTD];
    __shared__ float sc[Nn][OUTD];
    __shared__ float sGq[Nn*Nn], sGc[Nn*Nn];
    int tid = threadIdx.x;
    for (int i = tid; i < Nn*Nn; i += 256) { sGq[i] = g_Gqn[i]; sGc[i] = g_Gcn[i]; }
    for (int i = tid; i < Nn*OUTD; i += 256) {
        int m = i >> 7, c = i & 127;
        sq[m][c] = g_pq[((size_t)(b*Nn) + m) * OUTD + c];
        sc[m][c] = g_pc[((size_t)(b*Nn) + m) * OUTD + c];
    }
    __syncthreads();
    for (int i = tid; i < Nn*OUTD; i += 256) {
        int n = i >> 7, c = i & 127;
        float s1 = 0.f, s2 = 0.f;
        #pragma unroll
        for (int m = 0; m < Nn; m++) {
            s1 += sGq[n*Nn+m] * sq[m][c];
            s2 += sGc[n*Nn+m] * sc[m][c];
        }
        size_t o = ((size_t)(b*Nn) + n) * OUTD + c;
        g_ys[o] = tanhf(s1);
        g_yc[o] = tanhf(s2);
    }
}

// ---------------- per-step: tiny heads + quaternion update, one warp per (b,n)
__global__ void khead(const float* __restrict__ W3, const float* __restrict__ b3,
                      const float* __restrict__ W6, const float* __restrict__ b6,
                      const int* __restrict__ T, float* __restrict__ out, int step)
{
    int wid  = (blockIdx.x * blockDim.x + threadIdx.x) >> 5;
    int lane = threadIdx.x & 31;
    if (wid >= BN_) return;
    int b = wid / Nn, n = wid % Nn;
    int t = T[n];
    float val = 0.f;
    if (lane < 3) {
        const float* ys = g_ys + (size_t)wid * OUTD;
        const float* w  = W3 + ((size_t)t*3 + lane) * OUTD;
        #pragma unroll 8
        for (int k = 0; k < OUTD; k++) val += ys[k] * w[k];
        val += b3[n*3 + lane];
    } else if (lane < 9) {
        int a = lane - 3;
        const float* yc = g_yc + (size_t)wid * OUTD;
        const float* w  = W6 + ((size_t)t*6 + a) * OUTD;
        #pragma unroll 8
        for (int k = 0; k < OUTD; k++) val += yc[k] * w[k];
        val += b6[n*6 + a];
    }
    unsigned mask = 0xffffffffu;
    float v0 = __shfl_sync(mask, val, 0);
    float v1 = __shfl_sync(mask, val, 1);
    float v2 = __shfl_sync(mask, val, 2);
    float c0 = __shfl_sync(mask, val, 3);
    float c1 = __shfl_sync(mask, val, 4);
    float c2 = __shfl_sync(mask, val, 5);
    float c3 = __shfl_sync(mask, val, 6);
    float c4 = __shfl_sync(mask, val, 7);
    float c5 = __shfl_sync(mask, val, 8);
    if (lane == 0) {
        // quat_exp
        float theta = sqrtf(v0*v0 + v1*v1 + v2*v2);
        float w1 = cosf(0.5f * theta);
        float kk = (theta > 1e-8f) ? (sinf(0.5f*theta) / fmaxf(theta, 1e-8f)) : 0.5f;
        float dq0 = w1, dq1 = kk*v0, dq2 = kk*v1, dq3 = kk*v2;
        // qmul(dq, q_c)
        float* qc = g_qc + (size_t)wid * 4;
        float qw = qc[0], qx = qc[1], qy = qc[2], qz = qc[3];
        float nw = dq0*qw - (dq1*qx + dq2*qy + dq3*qz);
        float nx = dq0*qx + qw*dq1 + (dq2*qz - dq3*qy);
        float ny = dq0*qy + qw*dq2 + (dq3*qx - dq1*qz);
        float nz = dq0*qz + qw*dq3 + (dq1*qy - dq2*qx);
        qc[0]=nw; qc[1]=nx; qc[2]=ny; qc[3]=nz;
        float* xc = g_xc + (size_t)wid * FEAT;
        xc[0]=nw; xc[1]=nx; xc[2]=ny; xc[3]=nz;
        xc[4]=dq0; xc[5]=dq1; xc[6]=dq2; xc[7]=dq3;
        size_t od = ((size_t)b * PHs + step) * Nn + n;
        out[OFF_DQ  + od*4 + 0] = dq0; out[OFF_DQ + od*4 + 1] = dq1;
        out[OFF_DQ  + od*4 + 2] = dq2; out[OFF_DQ + od*4 + 3] = dq3;
        out[OFF_COV + od*6 + 0] = c0;  out[OFF_COV + od*6 + 1] = c1;
        out[OFF_COV + od*6 + 2] = c2;  out[OFF_COV + od*6 + 3] = c3;
        out[OFF_COV + od*6 + 4] = c4;  out[OFF_COV + od*6 + 5] = c5;
    }
}

// ---------------- launch ----------------
extern "C" void kernel_launch(void* const* d_in, const int* in_sizes, int n_in,
                              void* d_out, int out_size)
{
    const float* x    = (const float*)d_in[0];
    const float* h    = (const float*)d_in[1];
    const float* z    = (const float*)d_in[2];
    const float* q_t  = (const float*)d_in[3];
    const int*   T    = (const int*)  d_in[4];
    // d_in[5] = ph (scalar, value 12 by problem spec)
    const float* W0   = (const float*)d_in[6];
    const float* b0   = (const float*)d_in[7];
    const float* G0   = (const float*)d_in[8];
    const float* Wih  = (const float*)d_in[9];
    const float* Whh  = (const float*)d_in[10];
    const float* bih  = (const float*)d_in[11];
    const float* bhh  = (const float*)d_in[12];
    const float* Grnn = (const float*)d_in[13];
    const float* GA   = (const float*)d_in[14];
    const float* Wq   = (const float*)d_in[15];
    const float* bq   = (const float*)d_in[16];
    const float* Gq   = (const float*)d_in[17];
    const float* Wc   = (const float*)d_in[18];
    const float* bc   = (const float*)d_in[19];
    const float* Gc   = (const float*)d_in[20];
    const float* W3   = (const float*)d_in[21];
    const float* b3   = (const float*)d_in[22];
    const float* W6   = (const float*)d_in[23];
    const float* b6   = (const float*)d_in[24];
    float* out = (float*)d_out;

    knorms<<<1, 128>>>(G0, Grnn, GA, Gq, Gc);

    {
        int total = BN_ * IN0_;
        kprep<<<(total + 255) / 256, 256>>>(x, h, z, q_t, out);
    }

    // rnn_h pre-mix: tmp0 = xin(328) * W0^T + b0
    kgemm<<<dim3(B_/64, HID_/64, Nn), 256>>>(0, IN0_, 0, W0, IN0_, 0, HID_, IN0_, b0, 0, T);
    kmix_rnnh<<<dim3(B_, HID_/64), 256>>>();

    // base_ih = h_z(320) * Wih[:,8:]^T + bih  (step-invariant)
    kgemm<<<dim3(B_/64, G3_/64, Nn), 256>>>(0, IN0_, FEAT, Wih, IN0_, FEAT, G3_, HZ_, bih, 1, T);

    for (int t = 0; t < PHs; t++) {
        int cur = t & 1;
        // hr = h_c * Whh^T + bhh  (the dominant GEMM)
        kgemm<<<dim3(B_/64, G3_/64, Nn), 256>>>(1 + cur, HID_, 0, Whh, HID_, 0, G3_, HID_, bhh, 2, T);
        kgates<<<dim3(B_, HID_/64), 256>>>(Wih, T, cur);
        // pq = y*Wq^T+bq ; pc = y*Wc^T+bc
        kgemm<<<dim3(B_/64, OUTD/64, Nn), 256>>>(3, HID_, 0, Wq, HID_, 0, OUTD, HID_, bq, 3, T);
        kgemm<<<dim3(B_/64, OUTD/64, Nn), 256>>>(3, HID_, 0, Wc, HID_, 0, OUTD, HID_, bc, 4, T);
        kmixout<<<B_, 256>>>();
        khead<<<(BN_*32 + 255)/256, 256>>>(W3, b3, W6, b6, T, out, t);
    }
}

// round 3
// speedup vs baseline: 2.2561x; 2.2561x over previous
#include <cuda_runtime.h>
#include <math.h>
#include <cstdint>

// ---------------- problem constants ----------------
#define B_    256
#define Nn    21
#define PHs   12
#define FEAT  8
#define INP_  256
#define LAT_  64
#define HID_  512
#define OUTD  128
#define NT_   4
#define IN0_  328   // FEAT + LAT + INP
#define HZ_   320   // LAT + INP
#define G3_   1536  // 3*HID
#define BN_   (B_*Nn)

// output packing: dq (B,PH,N,4) | cov (B,PH,N,6) | x_t (B,N,8)
#define OFF_DQ   0
#define OFF_COV  (B_*PHs*Nn*4)
#define OFF_XT   (OFF_COV + B_*PHs*Nn*6)

// ---------------- device scratch ----------------
__device__ float g_xin[BN_*IN0_];
__device__ float g_base[BN_*G3_];
__device__ float g_hr[BN_*G3_];
__device__ float g_tmp0[BN_*HID_];
__device__ float g_h[2][BN_*HID_];
__device__ float g_y[BN_*HID_];
__device__ float g_pqc[BN_*256];       // [pq(128) | pc(128)]
__device__ float g_ys[BN_*OUTD];
__device__ float g_yc[BN_*OUTD];
__device__ float g_xc[BN_*FEAT];
__device__ float g_qc[BN_*4];
__device__ float g_G0n[Nn*Nn], g_Gn[Nn*Nn], g_Gqn[Nn*Nn], g_Gcn[Nn*Nn];
__device__ float g_Wqc[NT_*256*HID_];  // stacked [Wq;Wc]
__device__ float g_bqc[Nn*256];

// ---------------- helpers ----------------
__device__ __forceinline__ float tf32r(float x) {
    float r; asm("cvt.rna.tf32.f32 %0, %1;" : "=f"(r) : "f"(x)); return r;
}
__device__ __forceinline__ void mma_tf32(float* d,
    uint32_t a0, uint32_t a1, uint32_t a2, uint32_t a3,
    uint32_t b0, uint32_t b1)
{
    asm volatile(
        "mma.sync.aligned.m16n8k8.row.col.f32.tf32.tf32.f32 "
        "{%0,%1,%2,%3}, {%4,%5,%6,%7}, {%8,%9}, {%0,%1,%2,%3};"
        : "+f"(d[0]), "+f"(d[1]), "+f"(d[2]), "+f"(d[3])
        : "r"(a0), "r"(a1), "r"(a2), "r"(a3), "r"(b0), "r"(b1));
}

// ---------------- small prep kernels ----------------
__global__ void knorms(const float* __restrict__ G0, const float* __restrict__ Grnn,
                       const float* __restrict__ GA, const float* __restrict__ Gq,
                       const float* __restrict__ Gc)
{
    int i = threadIdx.x;
    if (i >= 4*Nn) return;
    int mat = i / Nn, r = i % Nn;
    const float* src = (mat==0)?G0:(mat==1)?Grnn:(mat==2)?Gq:Gc;
    float* dst = (mat==0)?g_G0n:(mat==1)?g_Gn:(mat==2)?g_Gqn:g_Gcn;
    float s = 0.f;
    for (int m = 0; m < Nn; m++) s += fabsf(src[r*Nn+m]);
    s = fmaxf(s, 1e-12f);
    for (int m = 0; m < Nn; m++) {
        float v = src[r*Nn+m] / s;
        if (mat == 1) v += GA[r*Nn+m];
        dst[r*Nn+m] = v;
    }
}

__global__ void kprep(const float* __restrict__ x, const float* __restrict__ h,
                      const float* __restrict__ z, const float* __restrict__ qt,
                      float* __restrict__ out)
{
    int idx = blockIdx.x * blockDim.x + threadIdx.x;
    if (idx < BN_*IN0_) {
        int bn = idx / IN0_, k = idx % IN0_;
        int b = bn / Nn, n = bn % Nn;
        float v;
        if (k < FEAT)            v = x[((b*2 + 0)*Nn + n)*FEAT + k];
        else if (k < FEAT+LAT_)  v = z[bn*LAT_ + (k - FEAT)];
        else                     v = h[bn*INP_ + (k - FEAT - LAT_)];
        g_xin[idx] = v;
    }
    if (idx < BN_*FEAT) {
        int bn = idx / FEAT, f = idx % FEAT;
        int b = bn / Nn, n = bn % Nn;
        float xv = x[((b*2 + 1)*Nn + n)*FEAT + f];
        g_xc[idx] = xv;
        out[OFF_XT + idx] = xv;
    }
    if (idx < BN_*4) g_qc[idx] = qt[idx];
}

__global__ void kbuildwqc(const float* __restrict__ Wq, const float* __restrict__ Wc,
                          const float* __restrict__ bq, const float* __restrict__ bc)
{
    int idx = blockIdx.x * blockDim.x + threadIdx.x;
    if (idx < NT_*256*HID_) {
        int t = idx / (256*HID_);
        int r = (idx / HID_) % 256;
        int k = idx % HID_;
        g_Wqc[idx] = (r < 128) ? Wq[((size_t)t*128 + r)*HID_ + k]
                               : Wc[((size_t)t*128 + (r-128))*HID_ + k];
    }
    if (idx < Nn*256) {
        int n = idx / 256, c = idx % 256;
        g_bqc[idx] = (c < 128) ? bq[n*128 + c] : bc[n*128 + (c-128)];
    }
}

// ---------------- mma.sync tf32 GEMM ----------------
// C[(b,n),g] = bias[n,g] + sum_k A[(b,n),aoff+k] * W[T[n],g,woff+k]
// CTA tile 128(M:batch) x 128(G), BK=32. grid=(M/128, G/128, Nn). 8 warps.
// smem k-layout permuted: p(k) = (k&24) | ((k&3)<<1) | ((k>>2)&1)
// so that fragment (k, k+4) pairs are contiguous -> LDS.64 fragment loads.
#define KSTR 40   // padded row stride (floats)

__global__ void __launch_bounds__(256) ktc(
    int asel, int lda, int aoff,
    const float* __restrict__ Wg, int ldw, int woff,
    int G, int K,
    const float* __restrict__ biasg, int csel,
    const int* __restrict__ T)
{
    __shared__ float As[128*KSTR];
    __shared__ float Bs[128*KSTR];

    const float* A = (asel==0)?g_xin : (asel==1)?g_h[0] : (asel==2)?g_h[1] : g_y;
    const float* W = Wg ? Wg : g_Wqc;
    const float* bias = biasg ? biasg : g_bqc;
    float* C = (csel==0)?g_tmp0 : (csel==1)?g_base : (csel==2)?g_hr : g_pqc;

    int n  = blockIdx.z;
    int t  = T[n];
    int b0 = blockIdx.x * 128;
    int g0 = blockIdx.y * 128;
    int tid  = threadIdx.x;
    int wid  = tid >> 5, lane = tid & 31;
    int wm = wid >> 1, wn = wid & 1;          // 4x2 warp grid; warp tile 32x64
    int gq = lane >> 2, tg = lane & 3;        // groupID, threadID-in-group

    const float* An = A + ((size_t)b0 * Nn + n) * lda + aoff;
    const float* Wt = W + ((size_t)t * G + g0) * ldw + woff;
    const size_t strideA = (size_t)Nn * lda;

    // staging indices (reused every tile)
    int sr = tid >> 3;            // row 0..127 (per 256-thread pass covers 32 rows x.. )
    int sq = tid & 7;             // quad index 0..7 -> k = 4*sq..4*sq+3
    int sp = ((sq >> 1) << 3) + (sq & 1);   // permuted base: 8s + t

    float acc[2][8][4];
    #pragma unroll
    for (int a = 0; a < 2; a++)
        #pragma unroll
        for (int b = 0; b < 8; b++)
            #pragma unroll
            for (int c = 0; c < 4; c++) acc[a][b][c] = 0.f;

    int ntiles = (K + 31) / 32;
    float4 pa[4], pb[4];

    // prefetch tile 0
    {
        int k = sq * 4;
        #pragma unroll
        for (int i = 0; i < 4; i++) {
            int r = sr + i * 32;
            pa[i] = (k < K) ? *(const float4*)(An + (size_t)r * strideA + k)
                            : make_float4(0.f,0.f,0.f,0.f);
            pb[i] = (k < K) ? *(const float4*)(Wt + (size_t)r * ldw + k)
                            : make_float4(0.f,0.f,0.f,0.f);
        }
    }

    for (int kt = 0; kt < ntiles; kt++) {
        // store staged tile (tf32-convert + k-permute)
        #pragma unroll
        for (int i = 0; i < 4; i++) {
            int r = sr + i * 32;
            float* ar = As + r * KSTR + sp;
            ar[0] = tf32r(pa[i].x); ar[2] = tf32r(pa[i].y);
            ar[4] = tf32r(pa[i].z); ar[6] = tf32r(pa[i].w);
            float* br = Bs + r * KSTR + sp;
            br[0] = tf32r(pb[i].x); br[2] = tf32r(pb[i].y);
            br[4] = tf32r(pb[i].z); br[6] = tf32r(pb[i].w);
        }
        __syncthreads();

        // prefetch next tile
        if (kt + 1 < ntiles) {
            int k = (kt + 1) * 32 + sq * 4;
            #pragma unroll
            for (int i = 0; i < 4; i++) {
                int r = sr + i * 32;
                pa[i] = (k < K) ? *(const float4*)(An + (size_t)r * strideA + k)
                                : make_float4(0.f,0.f,0.f,0.f);
                pb[i] = (k < K) ? *(const float4*)(Wt + (size_t)r * ldw + k)
                                : make_float4(0.f,0.f,0.f,0.f);
            }
        }

        // compute: 4 k-slices of 8
        #pragma unroll
        for (int s = 0; s < 4; s++) {
            int p0 = s * 8 + tg * 2;
            float2 alo[2], ahi[2];
            #pragma unroll
            for (int mt = 0; mt < 2; mt++) {
                int row = wm * 32 + mt * 16 + gq;
                alo[mt] = *(const float2*)(As + row * KSTR + p0);
                ahi[mt] = *(const float2*)(As + (row + 8) * KSTR + p0);
            }
            #pragma unroll
            for (int nt = 0; nt < 8; nt++) {
                int col = wn * 64 + nt * 8 + gq;
                float2 bf = *(const float2*)(Bs + col * KSTR + p0);
                uint32_t bb0 = __float_as_uint(bf.x), bb1 = __float_as_uint(bf.y);
                #pragma unroll
                for (int mt = 0; mt < 2; mt++) {
                    mma_tf32(acc[mt][nt],
                             __float_as_uint(alo[mt].x), __float_as_uint(ahi[mt].x),
                             __float_as_uint(alo[mt].y), __float_as_uint(ahi[mt].y),
                             bb0, bb1);
                }
            }
        }
        __syncthreads();
    }

    // epilogue: add bias, store
    const float* bp = bias + (size_t)n * G + g0;
    #pragma unroll
    for (int mt = 0; mt < 2; mt++) {
        int row = b0 + wm * 32 + mt * 16 + gq;
        float* C0 = C + ((size_t)row * Nn + n) * G + g0;
        float* C1 = C + ((size_t)(row + 8) * Nn + n) * G + g0;
        #pragma unroll
        for (int nt = 0; nt < 8; nt++) {
            int col = wn * 64 + nt * 8 + tg * 2;
            float2 o0, o1;
            o0.x = acc[mt][nt][0] + bp[col];
            o0.y = acc[mt][nt][1] + bp[col + 1];
            o1.x = acc[mt][nt][2] + bp[col];
            o1.y = acc[mt][nt][3] + bp[col + 1];
            *(float2*)(C0 + col) = o0;
            *(float2*)(C1 + col) = o1;
        }
    }
}

// ---------------- rnn_h init mix ----------------
__global__ void kmix_rnnh()
{
    int b = blockIdx.x, c0 = blockIdx.y * 64;
    __shared__ float sh[Nn][64];
    __shared__ float sG[Nn*Nn];
    int tid = threadIdx.x;
    for (int i = tid; i < Nn*Nn; i += 256) sG[i] = g_G0n[i];
    for (int i = tid; i < Nn*64; i += 256) {
        int m = i >> 6, c = i & 63;
        sh[m][c] = g_tmp0[((size_t)(b*Nn) + m) * HID_ + c0 + c];
    }
    __syncthreads();
    for (int i = tid; i < Nn*64; i += 256) {
        int n = i >> 6, c = i & 63;
        float s = 0.f;
        #pragma unroll
        for (int m = 0; m < Nn; m++) s += sG[n*Nn+m] * sh[m][c];
        g_h[0][((size_t)(b*Nn) + n) * HID_ + c0 + c] = s;
    }
}

// ---------------- per-step: graph mix + GRU gates ----------------
__global__ void kgates(const float* __restrict__ Wih, const int* __restrict__ T, int cur)
{
    int b = blockIdx.x, c0 = blockIdx.y * 64;
    __shared__ float sx[3][Nn][64];
    __shared__ float shh[3][Nn][64];
    __shared__ float sG[Nn*Nn];
    int tid = threadIdx.x;
    for (int i = tid; i < Nn*Nn; i += 256) sG[i] = g_Gn[i];
    for (int i = tid; i < 3*Nn*64; i += 256) {
        int s = i / (Nn*64), rem = i % (Nn*64);
        int m = rem >> 6, c = rem & 63;
        int g = s*HID_ + c0 + c;
        int t = T[m];
        const float* wx = Wih + ((size_t)t * G3_ + g) * IN0_;
        const float* xc = g_xc + (b*Nn + m) * FEAT;
        float acc = g_base[((size_t)(b*Nn) + m) * G3_ + g];
        #pragma unroll
        for (int q = 0; q < FEAT; q++) acc += xc[q] * wx[q];
        sx[s][m][c]  = acc;
        shh[s][m][c] = g_hr[((size_t)(b*Nn) + m) * G3_ + g];
    }
    __syncthreads();
    for (int i = tid; i < Nn*64; i += 256) {
        int n = i >> 6, c = i & 63;
        float ir=0,iz=0,ic=0,hr_=0,hz2=0,hc2=0;
        #pragma unroll
        for (int m = 0; m < Nn; m++) {
            float gw = sG[n*Nn+m];
            ir  += gw*sx[0][m][c];  iz  += gw*sx[1][m][c];  ic  += gw*sx[2][m][c];
            hr_ += gw*shh[0][m][c]; hz2 += gw*shh[1][m][c]; hc2 += gw*shh[2][m][c];
        }
        float r  = 1.f / (1.f + expf(-(ir + hr_)));
        float zg = 1.f / (1.f + expf(-(iz + hz2)));
        float nn = tanhf(ic + r*hc2);
        size_t hidx = ((size_t)(b*Nn) + n) * HID_ + c0 + c;
        float hc = g_h[cur][hidx];
        float hnew = (1.f - zg)*nn + zg*hc;
        g_h[cur^1][hidx] = hnew;
        g_y[hidx] = tanhf(hnew);
    }
}

// ---------------- per-step: output mixes ----------------
__global__ void kmixout()
{
    int b = blockIdx.x;
    __shared__ float sq[Nn][OUTD];
    __shared__ float sc[Nn][OUTD];
    __shared__ float sGq[Nn*Nn], sGc[Nn*Nn];
    int tid = threadIdx.x;
    for (int i = tid; i < Nn*Nn; i += 256) { sGq[i] = g_Gqn[i]; sGc[i] = g_Gcn[i]; }
    for (int i = tid; i < Nn*OUTD; i += 256) {
        int m = i >> 7, c = i & 127;
        sq[m][c] = g_pqc[((size_t)(b*Nn) + m) * 256 + c];
        sc[m][c] = g_pqc[((size_t)(b*Nn) + m) * 256 + 128 + c];
    }
    __syncthreads();
    for (int i = tid; i < Nn*OUTD; i += 256) {
        int n = i >> 7, c = i & 127;
        float s1 = 0.f, s2 = 0.f;
        #pragma unroll
        for (int m = 0; m < Nn; m++) {
            s1 += sGq[n*Nn+m] * sq[m][c];
            s2 += sGc[n*Nn+m] * sc[m][c];
        }
        size_t o = ((size_t)(b*Nn) + n) * OUTD + c;
        g_ys[o] = tanhf(s1);
        g_yc[o] = tanhf(s2);
    }
}

// ---------------- per-step: heads + quaternion ----------------
__global__ void khead(const float* __restrict__ W3, const float* __restrict__ b3,
                      const float* __restrict__ W6, const float* __restrict__ b6,
                      const int* __restrict__ T, float* __restrict__ out, int step)
{
    int wid  = (blockIdx.x * blockDim.x + threadIdx.x) >> 5;
    int lane = threadIdx.x & 31;
    if (wid >= BN_) return;
    int b = wid / Nn, n = wid % Nn;
    int t = T[n];
    float val = 0.f;
    if (lane < 3) {
        const float* ys = g_ys + (size_t)wid * OUTD;
        const float* w  = W3 + ((size_t)t*3 + lane) * OUTD;
        #pragma unroll 8
        for (int k = 0; k < OUTD; k++) val += ys[k] * w[k];
        val += b3[n*3 + lane];
    } else if (lane < 9) {
        int a = lane - 3;
        const float* yc = g_yc + (size_t)wid * OUTD;
        const float* w  = W6 + ((size_t)t*6 + a) * OUTD;
        #pragma unroll 8
        for (int k = 0; k < OUTD; k++) val += yc[k] * w[k];
        val += b6[n*6 + a];
    }
    unsigned mask = 0xffffffffu;
    float v0 = __shfl_sync(mask, val, 0);
    float v1 = __shfl_sync(mask, val, 1);
    float v2 = __shfl_sync(mask, val, 2);
    float c0 = __shfl_sync(mask, val, 3);
    float c1 = __shfl_sync(mask, val, 4);
    float c2 = __shfl_sync(mask, val, 5);
    float c3 = __shfl_sync(mask, val, 6);
    float c4 = __shfl_sync(mask, val, 7);
    float c5 = __shfl_sync(mask, val, 8);
    if (lane == 0) {
        float theta = sqrtf(v0*v0 + v1*v1 + v2*v2);
        float w1 = cosf(0.5f * theta);
        float kk = (theta > 1e-8f) ? (sinf(0.5f*theta) / fmaxf(theta, 1e-8f)) : 0.5f;
        float dq0 = w1, dq1 = kk*v0, dq2 = kk*v1, dq3 = kk*v2;
        float* qc = g_qc + (size_t)wid * 4;
        float qw = qc[0], qx = qc[1], qy = qc[2], qz = qc[3];
        float nw = dq0*qw - (dq1*qx + dq2*qy + dq3*qz);
        float nx = dq0*qx + qw*dq1 + (dq2*qz - dq3*qy);
        float ny = dq0*qy + qw*dq2 + (dq3*qx - dq1*qz);
        float nz = dq0*qz + qw*dq3 + (dq1*qy - dq2*qx);
        qc[0]=nw; qc[1]=nx; qc[2]=ny; qc[3]=nz;
        float* xc = g_xc + (size_t)wid * FEAT;
        xc[0]=nw; xc[1]=nx; xc[2]=ny; xc[3]=nz;
        xc[4]=dq0; xc[5]=dq1; xc[6]=dq2; xc[7]=dq3;
        size_t od = ((size_t)b * PHs + step) * Nn + n;
        out[OFF_DQ  + od*4 + 0] = dq0; out[OFF_DQ + od*4 + 1] = dq1;
        out[OFF_DQ  + od*4 + 2] = dq2; out[OFF_DQ + od*4 + 3] = dq3;
        out[OFF_COV + od*6 + 0] = c0;  out[OFF_COV + od*6 + 1] = c1;
        out[OFF_COV + od*6 + 2] = c2;  out[OFF_COV + od*6 + 3] = c3;
        out[OFF_COV + od*6 + 4] = c4;  out[OFF_COV + od*6 + 5] = c5;
    }
}

// ---------------- launch ----------------
extern "C" void kernel_launch(void* const* d_in, const int* in_sizes, int n_in,
                              void* d_out, int out_size)
{
    const float* x    = (const float*)d_in[0];
    const float* h    = (const float*)d_in[1];
    const float* z    = (const float*)d_in[2];
    const float* q_t  = (const float*)d_in[3];
    const int*   T    = (const int*)  d_in[4];
    const float* W0   = (const float*)d_in[6];
    const float* b0p  = (const float*)d_in[7];
    const float* G0   = (const float*)d_in[8];
    const float* Wih  = (const float*)d_in[9];
    const float* Whh  = (const float*)d_in[10];
    const float* bih  = (const float*)d_in[11];
    const float* bhh  = (const float*)d_in[12];
    const float* Grnn = (const float*)d_in[13];
    const float* GA   = (const float*)d_in[14];
    const float* Wq   = (const float*)d_in[15];
    const float* bq   = (const float*)d_in[16];
    const float* Gq   = (const float*)d_in[17];
    const float* Wc   = (const float*)d_in[18];
    const float* bc   = (const float*)d_in[19];
    const float* Gc   = (const float*)d_in[20];
    const float* W3   = (const float*)d_in[21];
    const float* b3   = (const float*)d_in[22];
    const float* W6   = (const float*)d_in[23];
    const float* b6   = (const float*)d_in[24];
    float* out = (float*)d_out;

    knorms<<<1, 128>>>(G0, Grnn, GA, Gq, Gc);
    {
        int total = BN_ * IN0_;
        kprep<<<(total + 255) / 256, 256>>>(x, h, z, q_t, out);
    }
    kbuildwqc<<<(NT_*256*HID_ + 255)/256, 256>>>(Wq, Wc, bq, bc);

    // rnn_h pre-mix: tmp0 = xin(328) @ W0^T + b0   (G=512)
    ktc<<<dim3(2, HID_/128, Nn), 256>>>(0, IN0_, 0, W0, IN0_, 0, HID_, IN0_, b0p, 0, T);
    kmix_rnnh<<<dim3(B_, HID_/64), 256>>>();

    // base_ih = h_z(320) @ Wih[:,8:]^T + bih   (G=1536, step-invariant)
    ktc<<<dim3(2, G3_/128, Nn), 256>>>(0, IN0_, FEAT, Wih, IN0_, FEAT, G3_, HZ_, bih, 1, T);

    for (int t = 0; t < PHs; t++) {
        int cur = t & 1;
        // hr = h_c @ Whh^T + bhh
        ktc<<<dim3(2, G3_/128, Nn), 256>>>(1 + cur, HID_, 0, Whh, HID_, 0, G3_, HID_, bhh, 2, T);
        kgates<<<dim3(B_, HID_/64), 256>>>(Wih, T, cur);
        // [pq|pc] = y @ [Wq;Wc]^T + [bq;bc]
        ktc<<<dim3(2, 256/128, Nn), 256>>>(3, HID_, 0, nullptr, HID_, 0, 256, HID_, nullptr, 3, T);
        kmixout<<<B_, 256>>>();
        khead<<<(BN_*32 + 255)/256, 256>>>(W3, b3, W6, b6, T, out, t);
    }
}